// round 6
// baseline (speedup 1.0000x reference)
#include <cuda_runtime.h>

// Problem shape (fixed by setup_inputs)
#define BQ 4
#define TT 96
#define NN 512
#define ROW_LEN 514              // [beta_logit, gamma_logit, z_0..z_511]
#define EPSV 1e-8f
#define BLKS_PER_BATCH 37        // 148 = 4 * 37 -> exactly 1 block per SM
#define GRID (BQ * BLKS_PER_BATCH)

// Scratch: ping-pong I vector + per-(b,t) barrier counters. S,I,R live in regs.
__device__ float    g_I[2][BQ][NN];
__device__ unsigned g_arrive[BQ * TT];

__global__ void reset_kernel() { g_arrive[threadIdx.x] = 0u; }

// ---------------------------------------------------------------------------
// Fused persistent kernel, 148 blocks x 512 threads. Warp-per-row.
// 3-stage software pipeline:
//   zc = c(t)        (softmax done during iter t-1; ready before barrier)
//   zn = params(t+1) (loads issued during iter t-1; softmaxed this iter)
//   zl = params(t+2) (loads issued this iter; in flight through the wait)
// Per-step critical path is only: barrier release -> I read -> dot -> update
// -> arrive. All softmax/exp/epi-store work hides under the barrier wait.
// ---------------------------------------------------------------------------
__global__ __launch_bounds__(512, 1)
void fused_kernel(const float* __restrict__ x0,
                  const float* __restrict__ params,
                  float* __restrict__ out_view,
                  float* __restrict__ epi) {
    const int blk      = blockIdx.x;
    const int b        = blk / BLKS_PER_BATCH;
    const int jloc     = blk - b * BLKS_PER_BATCH;
    const int rowStart = (jloc * NN) / BLKS_PER_BATCH;
    const int rowEnd   = ((jloc + 1) * NN) / BLKS_PER_BATCH;
    const int tid  = threadIdx.x;
    const int lane = tid & 31;
    const int wid  = tid >> 5;               // 16 warps, up to 14 active
    const int row  = rowStart + wid;
    const bool active = (row < rowEnd);

    __shared__ float I_sh[NN];

    // Persistent SIR state in lane-0 registers
    float S = 0.f, I = 0.f, R = 0.f;
    if (active && lane == 0) {
        const float* xr = x0 + (size_t)(b * NN + row) * 3;
        S = xr[0]; I = xr[1]; R = xr[2];
    }

    const size_t rowStride = (size_t)NN * ROW_LEN;            // per-t stride
    const size_t base0 = ((size_t)(b * TT) * NN + row) * ROW_LEN;

    // -------- prologue: c(0) fully computed; params(1) loads issued --------
    float2 zc[8]; float betaC = 0.f, gammaC = 0.f;            // c(t)
    float2 zn[8]; float bgn = 0.f;                            // raw params(t+1)
    if (active) {
        const float* p0 = params + base0;
        const float2* p2 = (const float2*)(p0 + 2);
#pragma unroll
        for (int k = 0; k < 8; k++) zc[k] = __ldcs(p2 + lane + 32 * k);
        float bg0 = (lane < 2) ? __ldcs(p0 + lane) : 0.f;

        const float* p1 = p0 + rowStride;
        const float2* p12 = (const float2*)(p1 + 2);
#pragma unroll
        for (int k = 0; k < 8; k++) zn[k] = __ldcs(p12 + lane + 32 * k);
        if (lane < 2) bgn = __ldcs(p1 + lane);

        // softmax + sigmoid for t=0, store epi(0)
        float mx = -3.4e38f;
#pragma unroll
        for (int k = 0; k < 8; k++) mx = fmaxf(mx, fmaxf(zc[k].x, zc[k].y));
#pragma unroll
        for (int off = 16; off; off >>= 1)
            mx = fmaxf(mx, __shfl_xor_sync(0xffffffffu, mx, off));
        float s = 0.f;
#pragma unroll
        for (int k = 0; k < 8; k++) {
            zc[k].x = __expf(zc[k].x - mx);
            zc[k].y = __expf(zc[k].y - mx);
            s += zc[k].x + zc[k].y;
        }
#pragma unroll
        for (int off = 16; off; off >>= 1)
            s += __shfl_xor_sync(0xffffffffu, s, off);
        const float inv = 1.0f / s;

        float* o = epi + base0;
        float sb = 0.f;
        if (lane < 2) {
            sb = 1.0f / (1.0f + __expf(-bg0));
            __stcs(o + lane, sb);
        }
        float2* o2 = (float2*)(o + 2);
#pragma unroll
        for (int k = 0; k < 8; k++) {
            zc[k].x *= inv; zc[k].y *= inv;
            __stcs(o2 + lane + 32 * k, zc[k]);
        }
        betaC  = __shfl_sync(0xffffffffu, sb, 0);
        gammaC = __shfl_sync(0xffffffffu, sb, 1);
    }

    for (int t = 0; t < TT; t++) {
        // ---- 1) issue loads for params(t+2) (longest latency first) ----
        float2 zl[8]; float bgl = 0.f;
        if (active && t + 2 < TT) {
            const float* pl = params + base0 + (size_t)(t + 2) * rowStride;
            const float2* pl2 = (const float2*)(pl + 2);
#pragma unroll
            for (int k = 0; k < 8; k++) zl[k] = __ldcs(pl2 + lane + 32 * k);
            if (lane < 2) bgl = __ldcs(pl + lane);
        }

        // ---- 2) softmax(t+1) from zn; store epi(t+1); off t's chain ----
        float betaN = 0.f, gammaN = 0.f;
        if (active && t + 1 < TT) {
            float mx = -3.4e38f;
#pragma unroll
            for (int k = 0; k < 8; k++) mx = fmaxf(mx, fmaxf(zn[k].x, zn[k].y));
#pragma unroll
            for (int off = 16; off; off >>= 1)
                mx = fmaxf(mx, __shfl_xor_sync(0xffffffffu, mx, off));
            float s = 0.f;
#pragma unroll
            for (int k = 0; k < 8; k++) {
                zn[k].x = __expf(zn[k].x - mx);
                zn[k].y = __expf(zn[k].y - mx);
                s += zn[k].x + zn[k].y;
            }
#pragma unroll
            for (int off = 16; off; off >>= 1)
                s += __shfl_xor_sync(0xffffffffu, s, off);
            const float inv = 1.0f / s;

            float* o = epi + base0 + (size_t)(t + 1) * rowStride;
            float sb = 0.f;
            if (lane < 2) {
                sb = 1.0f / (1.0f + __expf(-bgn));
                __stcs(o + lane, sb);
            }
            float2* o2 = (float2*)(o + 2);
#pragma unroll
            for (int k = 0; k < 8; k++) {
                zn[k].x *= inv; zn[k].y *= inv;
                __stcs(o2 + lane + 32 * k, zn[k]);
            }
            betaN  = __shfl_sync(0xffffffffu, sb, 0);
            gammaN = __shfl_sync(0xffffffffu, sb, 1);
        }

        // ---- 3) wait for step t-1 (2 steps of loads + stores in flight) ----
        if (t > 0) {
            if (tid == 0) {
                volatile unsigned* vf = g_arrive + (b * TT + t - 1);
                while (*vf < BLKS_PER_BATCH) { }
                __threadfence();                   // acquire
            }
            __syncthreads();                       // also guards I_sh reuse
        }

        // ---- I(t-1) -> shared ----
        if (t == 0) {
            for (int i = tid; i < NN; i += 512)
                I_sh[i] = x0[(b * NN + i) * 3 + 1];
        } else if (tid < NN / 2) {
            const float2* Ij = (const float2*)&g_I[t & 1][b][0];
            ((float2*)I_sh)[tid] = __ldcg(Ij + tid);
        }
        __syncthreads();

        // ---- 4) dot with c(t) regs + SIR update ----
        if (active) {
            const float2* I2 = (const float2*)I_sh;
            float acc = 0.f;
#pragma unroll
            for (int k = 0; k < 8; k++) {
                const float2 iv = I2[lane + 32 * k];
                acc = fmaf(zc[k].x, iv.x, fmaf(zc[k].y, iv.y, acc));
            }
#pragma unroll
            for (int off = 16; off; off >>= 1)
                acc += __shfl_xor_sync(0xffffffffu, acc, off);

            if (lane == 0) {
                const float Np = fmaxf(S + I + R, EPSV);
                const float dS = -(betaC * S * acc) / Np;
                const float dR = gammaC * I;
                const float dI = -dS - dR;
                float St = fmaxf(S + dS, 0.f);
                float It = fmaxf(I + dI, 0.f);
                float Rt = fmaxf(R + dR, 0.f);
                const float scale = Np / fmaxf(St + It + Rt, EPSV);
                S = St * scale; I = It * scale; R = Rt * scale;

                g_I[(t + 1) & 1][b][row] = I;

                const size_t ov = ((size_t)(b * TT + t) * NN + row) * 3;
                __stcs(out_view + ov,     S);
                __stcs(out_view + ov + 1, I);
                __stcs(out_view + ov + 2, R);
            }
        }

        // ---- 5) publish + arrive ----
        __syncthreads();
        if (t < TT - 1 && tid == 0) {
            __threadfence();                       // release
            atomicAdd(&g_arrive[b * TT + t], 1u);
        }

        // ---- rotate pipeline ----
        betaC = betaN; gammaC = gammaN;
#pragma unroll
        for (int k = 0; k < 8; k++) { zc[k] = zn[k]; zn[k] = zl[k]; }
        bgn = bgl;
    }
}

// ---------------------------------------------------------------------------
// Launch
// ---------------------------------------------------------------------------
extern "C" void kernel_launch(void* const* d_in, const int* in_sizes, int n_in,
                              void* d_out, int out_size) {
    const float* x0;
    const float* params;
    if (in_sizes[0] == BQ * NN * 3) {
        x0     = (const float*)d_in[0];
        params = (const float*)d_in[1];
    } else {
        x0     = (const float*)d_in[1];
        params = (const float*)d_in[0];
    }

    float* out      = (float*)d_out;
    float* out_view = out;                              // (B,T,N,3)
    float* epi      = out + (size_t)BQ * TT * NN * 3;   // (B,T,N,514)

    reset_kernel<<<1, BQ * TT>>>();
    fused_kernel<<<GRID, 512>>>(x0, params, out_view, epi);
}